// round 7
// baseline (speedup 1.0000x reference)
#include <cuda_runtime.h>
#include <cstdint>

// out[b,c,h,w] = x[b,c,2h,2w] * 0.5f     (Haar DWT subband sum collapses to this)
// x:  [16, 64, 512, 512] fp32,  out: [16, 64, 256, 256] fp32
//
// Warp-coalesced geometry (same as R4/R5):
//   pair index p in [0, 33'554'432):  out float2 index = p
//   pair  = p & 127          (128 float2 per output row)
//   orow  = (p >> 7) & 255
//   bc    = p >> 15
//   input float4 index = bc*65536 + orow*256 + pair   (even input row 2*orow)
//
// MLP=8: each block owns 2048 consecutive pairs; thread t processes
// pairs base+t+{0,256,...,1792}. Every LDG.128 is 512B-contiguous per warp,
// every STG.64 coalesced. All eight loads front-batched for max queue depth.

__device__ __forceinline__ long long pair_to_in_idx(unsigned p)
{
    unsigned pair = p & 127u;
    unsigned orow = (p >> 7) & 255u;
    unsigned bc   = p >> 15;
    return ((long long)bc << 16) + ((long long)orow << 8) + pair;
}

__global__ __launch_bounds__(256) void haar_sum_kernel(
    const float4* __restrict__ x, float2* __restrict__ out)
{
    const unsigned base = blockIdx.x * 2048u + threadIdx.x;

    unsigned idx[8];
    long long a[8];
#pragma unroll
    for (int k = 0; k < 8; k++) {
        idx[k] = base + k * 256u;
        a[k]   = pair_to_in_idx(idx[k]);
    }

    // eight independent streaming loads in flight
    float4 v[8];
#pragma unroll
    for (int k = 0; k < 8; k++)
        v[k] = __ldcs(&x[a[k]]);

#pragma unroll
    for (int k = 0; k < 8; k++) {
        float2 o;
        o.x = v[k].x * 0.5f;
        o.y = v[k].z * 0.5f;
        __stcs(&out[idx[k]], o);
    }
}

extern "C" void kernel_launch(void* const* d_in, const int* in_sizes, int n_in,
                              void* d_out, int out_size)
{
    const float4* x = (const float4*)d_in[0];
    float2* out     = (float2*)d_out;

    // out_size = 67,108,864 floats -> 33,554,432 pairs -> 2048 pairs per block
    long long n_pairs = (long long)out_size / 2;
    long long blocks  = n_pairs / 2048;                // 16384

    haar_sum_kernel<<<(unsigned)blocks, 256>>>(x, out);
}